// round 1
// baseline (speedup 1.0000x reference)
#include <cuda_runtime.h>
#include <math.h>

// Problem constants
#define GB 4
#define GN 2048
#define GDIM 1024
#define GHEADS 16
#define GDH 64
#define GINNER 1024
#define M_ROWS (GB * GN)          // 8192
#define QKV_COLS (3 * GINNER)     // 3072

// Scratch (allocation-free rule: __device__ globals)
__device__ float g_qkv[M_ROWS * QKV_COLS];   // [8192, 3072]  q|k|v
__device__ float g_attn[M_ROWS * GINNER];    // [8192, 1024]  attention output

// ---------------------------------------------------------------------------
// Tiled SGEMM: C[M,N] = A[M,K] @ B[K,N] (+ bias). 128x128 tile, BK=16,
// 256 threads, 8x8 microtile per thread. All dims divisible by tiles here.
// ---------------------------------------------------------------------------
#define BM 128
#define BN 128
#define BK 16

__global__ __launch_bounds__(256) void sgemm_kernel(
    const float* __restrict__ A, const float* __restrict__ B,
    const float* __restrict__ bias, float* __restrict__ C,
    int M, int N, int K)
{
    __shared__ float As[BK][BM + 4];   // transposed A tile, padded
    __shared__ float Bs[BK][BN];

    const int tid = threadIdx.x;
    const int rowBase = blockIdx.y * BM;
    const int colBase = blockIdx.x * BN;
    const int tx = tid & 15, ty = tid >> 4;
    const int r0 = ty * 8, c0 = tx * 8;

    float acc[8][8];
#pragma unroll
    for (int i = 0; i < 8; i++)
#pragma unroll
        for (int j = 0; j < 8; j++) acc[i][j] = 0.f;

    for (int k0 = 0; k0 < K; k0 += BK) {
        // A tile: 128 rows x 16 cols -> As[k][row]
#pragma unroll
        for (int i = 0; i < 2; i++) {
            int f = tid + i * 256;
            int r = f >> 2;              // 0..127
            int c4 = (f & 3) * 4;        // 0,4,8,12
            float4 v = *(const float4*)(A + (size_t)(rowBase + r) * K + k0 + c4);
            As[c4 + 0][r] = v.x;
            As[c4 + 1][r] = v.y;
            As[c4 + 2][r] = v.z;
            As[c4 + 3][r] = v.w;
        }
        // B tile: 16 rows x 128 cols -> Bs[k][col]
#pragma unroll
        for (int i = 0; i < 2; i++) {
            int f = tid + i * 256;
            int r = f >> 5;              // 0..15
            int c4 = (f & 31) * 4;
            *(float4*)&Bs[r][c4] =
                *(const float4*)(B + (size_t)(k0 + r) * N + colBase + c4);
        }
        __syncthreads();

#pragma unroll
        for (int kk = 0; kk < BK; kk++) {
            float af[8], bf[8];
#pragma unroll
            for (int i = 0; i < 8; i++) af[i] = As[kk][r0 + i];
            float4 b0 = *(float4*)&Bs[kk][c0];
            float4 b1 = *(float4*)&Bs[kk][c0 + 4];
            bf[0] = b0.x; bf[1] = b0.y; bf[2] = b0.z; bf[3] = b0.w;
            bf[4] = b1.x; bf[5] = b1.y; bf[6] = b1.z; bf[7] = b1.w;
#pragma unroll
            for (int i = 0; i < 8; i++)
#pragma unroll
                for (int j = 0; j < 8; j++)
                    acc[i][j] += af[i] * bf[j];
        }
        __syncthreads();
    }

#pragma unroll
    for (int i = 0; i < 8; i++) {
        int row = rowBase + r0 + i;
        float* cp = C + (size_t)row * N + colBase + c0;
        if (bias) {
#pragma unroll
            for (int j = 0; j < 8; j++) acc[i][j] += bias[colBase + c0 + j];
        }
        float4 o0 = make_float4(acc[i][0], acc[i][1], acc[i][2], acc[i][3]);
        float4 o1 = make_float4(acc[i][4], acc[i][5], acc[i][6], acc[i][7]);
        *(float4*)cp = o0;
        *(float4*)(cp + 4) = o1;
    }
}

// ---------------------------------------------------------------------------
// Flash attention: one CTA = one (batch*head, 64-query block).
// Streams 64-key tiles of K/V through smem with online softmax.
// d = 64. Q pre-scaled by 1/8. O accumulated in registers (4x4 per thread).
// ---------------------------------------------------------------------------
#define AP 68   // padded row stride for 64-wide smem tiles

__global__ __launch_bounds__(256) void flash_attn_kernel(
    const float* __restrict__ qkv, float* __restrict__ outp)
{
    extern __shared__ float sm[];
    float* sQt = sm;                  // [64 k][AP rows]  (transposed, pre-scaled)
    float* sKt = sQt + 64 * AP;       // [64 k][AP keys]  (transposed)
    float* sV  = sKt + 64 * AP;       // [64 keys][AP d]
    float* sS  = sV  + 64 * AP;       // [64 rows][AP keys] scores / probs
    float* sM  = sS  + 64 * AP;       // [64] running max
    float* sL  = sM + 64;             // [64] running denom
    float* sAl = sL + 64;             // [64] rescale factor

    const int tid = threadIdx.x;
    const int qblk = blockIdx.x;      // 0..31
    const int bh = blockIdx.y;        // 0..63
    const int b = bh >> 4, h = bh & 15;

    const size_t rowStride = QKV_COLS;                       // 3072
    const float* qb = qkv + (size_t)b * GN * rowStride + (size_t)h * GDH;
    const float* kb = qb + GINNER;
    const float* vb = qb + 2 * GINNER;

    // Load Q tile, transposed, scaled by d^-0.5 = 0.125 (exact)
#pragma unroll
    for (int i = 0; i < 4; i++) {
        int f = tid + i * 256;
        int r = f >> 4;               // 0..63
        int c4 = (f & 15) * 4;        // 0..60
        float4 v = *(const float4*)(qb + (size_t)(qblk * 64 + r) * rowStride + c4);
        sQt[(c4 + 0) * AP + r] = v.x * 0.125f;
        sQt[(c4 + 1) * AP + r] = v.y * 0.125f;
        sQt[(c4 + 2) * AP + r] = v.z * 0.125f;
        sQt[(c4 + 3) * AP + r] = v.w * 0.125f;
    }
    if (tid < 64) { sM[tid] = -3.0e38f; sL[tid] = 0.f; }

    const int tx = tid & 15, ty = tid >> 4;
    const int r0 = ty * 4, c0 = tx * 4;

    float o[4][4];
#pragma unroll
    for (int i = 0; i < 4; i++)
#pragma unroll
        for (int j = 0; j < 4; j++) o[i][j] = 0.f;

    for (int jj = 0; jj < GN / 64; jj++) {
        __syncthreads();   // prev PV done (and Q/init visible on first iter)

        // Load K (transposed) and V tiles
#pragma unroll
        for (int i = 0; i < 4; i++) {
            int f = tid + i * 256;
            int kr = f >> 4;
            int c4 = (f & 15) * 4;
            size_t g = (size_t)(jj * 64 + kr) * rowStride + c4;
            float4 kv = *(const float4*)(kb + g);
            sKt[(c4 + 0) * AP + kr] = kv.x;
            sKt[(c4 + 1) * AP + kr] = kv.y;
            sKt[(c4 + 2) * AP + kr] = kv.z;
            sKt[(c4 + 3) * AP + kr] = kv.w;
            float4 vv = *(const float4*)(vb + g);
            *(float4*)&sV[kr * AP + c4] = vv;
        }
        __syncthreads();

        // S = Q @ K^T  (each thread: 4x4 microtile)
        float s[4][4];
#pragma unroll
        for (int i = 0; i < 4; i++)
#pragma unroll
            for (int j = 0; j < 4; j++) s[i][j] = 0.f;

#pragma unroll 8
        for (int k = 0; k < 64; k++) {
            float4 qf = *(float4*)&sQt[k * AP + r0];
            float4 kf = *(float4*)&sKt[k * AP + c0];
            float qa[4] = {qf.x, qf.y, qf.z, qf.w};
            float ka[4] = {kf.x, kf.y, kf.z, kf.w};
#pragma unroll
            for (int i = 0; i < 4; i++)
#pragma unroll
                for (int j = 0; j < 4; j++)
                    s[i][j] += qa[i] * ka[j];
        }
#pragma unroll
        for (int i = 0; i < 4; i++)
#pragma unroll
            for (int j = 0; j < 4; j++)
                sS[(r0 + i) * AP + c0 + j] = s[i][j];
        __syncthreads();

        // Online softmax: 4 threads per row, 16 keys each
        {
            int row = tid >> 2, part = tid & 3;
            float* base = &sS[row * AP + part * 16];
            float mloc = -3.0e38f;
#pragma unroll
            for (int t = 0; t < 16; t++) mloc = fmaxf(mloc, base[t]);
            mloc = fmaxf(mloc, __shfl_xor_sync(0xffffffffu, mloc, 1));
            mloc = fmaxf(mloc, __shfl_xor_sync(0xffffffffu, mloc, 2));
            float mold = sM[row];
            float mnew = fmaxf(mold, mloc);
            float suml = 0.f;
#pragma unroll
            for (int t = 0; t < 16; t++) {
                float p = __expf(base[t] - mnew);
                base[t] = p;
                suml += p;
            }
            suml += __shfl_xor_sync(0xffffffffu, suml, 1);
            suml += __shfl_xor_sync(0xffffffffu, suml, 2);
            if (part == 0) {
                float al = __expf(mold - mnew);
                sAl[row] = al;
                sM[row] = mnew;
                sL[row] = sL[row] * al + suml;
            }
        }
        __syncthreads();

        // O = O * alpha + P @ V
        float alr[4];
#pragma unroll
        for (int i = 0; i < 4; i++) alr[i] = sAl[r0 + i];
#pragma unroll
        for (int i = 0; i < 4; i++)
#pragma unroll
            for (int j = 0; j < 4; j++) o[i][j] *= alr[i];

        for (int key = 0; key < 64; key += 4) {
            float4 p[4];
#pragma unroll
            for (int i = 0; i < 4; i++)
                p[i] = *(float4*)&sS[(r0 + i) * AP + key];
#pragma unroll
            for (int kk = 0; kk < 4; kk++) {
                float4 vf = *(float4*)&sV[(key + kk) * AP + c0];
#pragma unroll
                for (int i = 0; i < 4; i++) {
                    float w = ((const float*)&p[i])[kk];
                    o[i][0] += w * vf.x;
                    o[i][1] += w * vf.y;
                    o[i][2] += w * vf.z;
                    o[i][3] += w * vf.w;
                }
            }
        }
    }

    // Normalize and write: out[b, n, h*64 + d]
#pragma unroll
    for (int i = 0; i < 4; i++) {
        float inv = 1.f / sL[r0 + i];
        float4 ov = make_float4(o[i][0] * inv, o[i][1] * inv,
                                o[i][2] * inv, o[i][3] * inv);
        size_t idx = (size_t)(b * GN + qblk * 64 + r0 + i) * GINNER
                     + (size_t)h * GDH + c0;
        *(float4*)&outp[idx] = ov;
    }
}

// ---------------------------------------------------------------------------
// Launch: qkv GEMM -> flash attention -> output GEMM (+bias)
// ---------------------------------------------------------------------------
extern "C" void kernel_launch(void* const* d_in, const int* in_sizes, int n_in,
                              void* d_out, int out_size)
{
    const float* x     = (const float*)d_in[0];  // [4,2048,1024]
    const float* w_qkv = (const float*)d_in[1];  // [1024,3072]
    const float* w_out = (const float*)d_in[2];  // [1024,1024]
    const float* b_out = (const float*)d_in[3];  // [1024]
    float* out = (float*)d_out;                  // [4,2048,1024]

    float *qkv_p = nullptr, *attn_p = nullptr;
    cudaGetSymbolAddress((void**)&qkv_p, g_qkv);
    cudaGetSymbolAddress((void**)&attn_p, g_attn);

    dim3 blk(256);

    // 1) qkv = x @ w_qkv
    sgemm_kernel<<<dim3(QKV_COLS / BN, M_ROWS / BM), blk>>>(
        x, w_qkv, nullptr, qkv_p, M_ROWS, QKV_COLS, GDIM);

    // 2) flash attention
    size_t smem = (size_t)(4 * 64 * AP + 192) * sizeof(float);  // ~70.4 KB
    cudaFuncSetAttribute(flash_attn_kernel,
                         cudaFuncAttributeMaxDynamicSharedMemorySize, (int)smem);
    flash_attn_kernel<<<dim3(GN / 64, GB * GHEADS), blk, smem>>>(qkv_p, attn_p);

    // 3) out = attn @ w_out + b_out
    sgemm_kernel<<<dim3(GDIM / BN, M_ROWS / BM), blk>>>(
        attn_p, w_out, b_out, out, M_ROWS, GDIM, GINNER);
}

// round 3
// speedup vs baseline: 2.8067x; 2.8067x over previous
#include <cuda_runtime.h>
#include <math.h>
#include <stdint.h>

// Problem constants
#define GB 4
#define GN 2048
#define GDIM 1024
#define GHEADS 16
#define GDH 64
#define GINNER 1024
#define M_ROWS (GB * GN)          // 8192
#define QKV_COLS (3 * GINNER)     // 3072

// Scratch (__device__ globals; no allocations allowed)
__device__ float g_qkv[M_ROWS * QKV_COLS];     // [8192, 3072]
__device__ float g_attn[M_ROWS * GINNER];      // [8192, 1024] (tf32-rounded)
__device__ float g_xr[M_ROWS * GDIM];          // tf32-rounded x
__device__ float g_wqkvr[GDIM * QKV_COLS];     // tf32-rounded w_qkv [K,N]
__device__ float g_woutr[GINNER * GDIM];       // tf32-rounded w_out [K,N]

// ---------------------------------------------------------------------------
// Helpers (all compute_100-safe: sm_80-era PTX only)
// ---------------------------------------------------------------------------
__device__ __forceinline__ uint32_t smem_u32(const void* p) {
    uint32_t a;
    asm("{ .reg .u64 t; cvta.to.shared.u64 t, %1; cvt.u32.u64 %0, t; }"
        : "=r"(a) : "l"(p));
    return a;
}
__device__ __forceinline__ void cp_async16(uint32_t dst, const void* src) {
    asm volatile("cp.async.cg.shared.global [%0], [%1], 16;" :: "r"(dst), "l"(src));
}
#define CP_COMMIT() asm volatile("cp.async.commit_group;" ::: "memory")
template <int N>
__device__ __forceinline__ void cp_wait() {
    asm volatile("cp.async.wait_group %0;" :: "n"(N) : "memory");
}

// Round fp32 -> tf32 (round-to-nearest via integer trick; 2 ALU ops)
__device__ __forceinline__ float rtf(float x) {
    return __int_as_float((__float_as_int(x) + 0x1000) & 0xFFFFE000);
}

// Fast exp on the FMA pipe (no MUFU). Valid for x <= 0 (softmax deltas).
__device__ __forceinline__ float fast_exp(float x) {
    float y = fmaxf(x * 1.4426950408889634f, -126.0f);
    float t = y + 12582912.0f;                 // 1.5*2^23: round y to int
    int ni = __float_as_int(t) - 0x4B400000;   // integer part
    float f = y - (t - 12582912.0f);           // frac in [-0.5, 0.5]
    float p = 1.3333558146e-3f;
    p = fmaf(p, f, 9.6181291076e-3f);
    p = fmaf(p, f, 5.5504108665e-2f);
    p = fmaf(p, f, 2.4022650696e-1f);
    p = fmaf(p, f, 6.9314718056e-1f);
    p = fmaf(p, f, 1.0f);
    return __int_as_float(__float_as_int(p) + (ni << 23));
}
// Same, but result additionally rounded to tf32 (for P fed to mma)
__device__ __forceinline__ float fast_exp_tf32(float x) {
    float y = fmaxf(x * 1.4426950408889634f, -126.0f);
    float t = y + 12582912.0f;
    int ni = __float_as_int(t) - 0x4B400000;
    float f = y - (t - 12582912.0f);
    float p = 1.3333558146e-3f;
    p = fmaf(p, f, 9.6181291076e-3f);
    p = fmaf(p, f, 5.5504108665e-2f);
    p = fmaf(p, f, 2.4022650696e-1f);
    p = fmaf(p, f, 6.9314718056e-1f);
    p = fmaf(p, f, 1.0f);
    int bits = __float_as_int(p) + (ni << 23);
    return __int_as_float((bits + 0x1000) & 0xFFFFE000);
}

// m16n8k8 tf32 mma, D accumulates in place.
__device__ __forceinline__ void mma_tf32(float* d, const uint32_t* a, const uint32_t* b) {
    asm volatile(
        "mma.sync.aligned.m16n8k8.row.col.f32.tf32.tf32.f32 "
        "{%0,%1,%2,%3}, {%4,%5,%6,%7}, {%8,%9}, {%0,%1,%2,%3};"
        : "+f"(d[0]), "+f"(d[1]), "+f"(d[2]), "+f"(d[3])
        : "r"(a[0]), "r"(a[1]), "r"(a[2]), "r"(a[3]), "r"(b[0]), "r"(b[1]));
}

// ---------------------------------------------------------------------------
// tf32 tensor-core GEMM: C[M,N] = A[M,K] @ B[K,N] (+bias).
// A, B pre-rounded to tf32. CTA tile 128x128, BK=32, 8 warps (2m x 4n),
// warp tile 64x32, 3-stage cp.async pipeline.
// ---------------------------------------------------------------------------
#define A_PAD 36
#define B_PAD 136
#define A_F (128 * A_PAD)          // 4608 floats
#define B_F (32 * B_PAD)           // 4352 floats
#define STAGE_F (A_F + B_F)        // 8960 floats = 35840 B
#define GSMEM_BYTES (3 * STAGE_F * 4)   // 107520

__global__ __launch_bounds__(256, 2) void gemm_tf32_kernel(
    const float* __restrict__ A, const float* __restrict__ B,
    const float* __restrict__ bias, float* __restrict__ C,
    int M, int N, int K)
{
    extern __shared__ float smem[];
    const uint32_t sb = smem_u32(smem);

    const int tid = threadIdx.x;
    const int wid = tid >> 5, lane = tid & 31;
    const int wm = wid >> 2, wn = wid & 3;       // 2 x 4 warp grid
    const int l4 = lane >> 2, lm4 = lane & 3;

    const int nb = blockIdx.x, mb = blockIdx.y;
    const int rowBase = mb * 128, colBase = nb * 128;
    const float* Ag = A + (size_t)rowBase * K;
    const float* Bg = B + colBase;
    const int KT = K >> 5;

    float acc[4][4][4];
#pragma unroll
    for (int i = 0; i < 4; i++)
#pragma unroll
        for (int j = 0; j < 4; j++)
#pragma unroll
            for (int r = 0; r < 4; r++) acc[i][j][r] = 0.f;

    // ---- loader ----
#define LOAD_STAGE(kt, slot) do {                                            \
    uint32_t _sa = sb + (slot) * STAGE_F * 4;                                \
    uint32_t _sb2 = _sa + A_F * 4;                                           \
    _Pragma("unroll")                                                        \
    for (int _i = 0; _i < 4; _i++) {                                         \
        int _c = tid + _i * 256;                                             \
        int _r = _c >> 3, _kc = _c & 7;                                      \
        cp_async16(_sa + _r * (A_PAD * 4) + _kc * 16,                        \
                   Ag + (size_t)_r * K + (kt) * 32 + _kc * 4);               \
    }                                                                        \
    _Pragma("unroll")                                                        \
    for (int _i = 0; _i < 4; _i++) {                                         \
        int _c = tid + _i * 256;                                             \
        int _kr = _c >> 5, _nc = _c & 31;                                    \
        cp_async16(_sb2 + _kr * (B_PAD * 4) + _nc * 16,                      \
                   Bg + (size_t)((kt) * 32 + _kr) * N + _nc * 4);            \
    }                                                                        \
    CP_COMMIT();                                                             \
} while (0)

    LOAD_STAGE(0, 0);
    LOAD_STAGE(1, 1);
    LOAD_STAGE(2, 2);

    for (int k = 0; k < KT; k++) {
        if (k < KT - 2)       cp_wait<2>();
        else if (k == KT - 2) cp_wait<1>();
        else                  cp_wait<0>();
        __syncthreads();

        const float* As = smem + (k % 3) * STAGE_F;
        const float* Bs = As + A_F;

#pragma unroll
        for (int ks = 0; ks < 4; ks++) {
            uint32_t a[4][4], b[4][2];
            int kk = ks * 8 + lm4;
#pragma unroll
            for (int mf = 0; mf < 4; mf++) {
                int m = wm * 64 + mf * 16 + l4;
                const uint32_t* Au = (const uint32_t*)As;
                a[mf][0] = Au[m * A_PAD + kk];
                a[mf][1] = Au[(m + 8) * A_PAD + kk];
                a[mf][2] = Au[m * A_PAD + kk + 4];
                a[mf][3] = Au[(m + 8) * A_PAD + kk + 4];
            }
#pragma unroll
            for (int nf = 0; nf < 4; nf++) {
                int n = wn * 32 + nf * 8 + l4;
                const uint32_t* Bu = (const uint32_t*)Bs;
                b[nf][0] = Bu[kk * B_PAD + n];
                b[nf][1] = Bu[(kk + 4) * B_PAD + n];
            }
#pragma unroll
            for (int mf = 0; mf < 4; mf++)
#pragma unroll
                for (int nf = 0; nf < 4; nf++)
                    mma_tf32(acc[mf][nf], a[mf], b[nf]);
        }
        __syncthreads();

        if (k + 3 < KT) LOAD_STAGE(k + 3, k % 3);
    }
#undef LOAD_STAGE

    // Epilogue: direct float2 stores from C fragments
#pragma unroll
    for (int mf = 0; mf < 4; mf++) {
        int row0 = rowBase + wm * 64 + mf * 16 + l4;
#pragma unroll
        for (int nf = 0; nf < 4; nf++) {
            int col = colBase + wn * 32 + nf * 8 + lm4 * 2;
            float b0 = 0.f, b1 = 0.f;
            if (bias) { b0 = bias[col]; b1 = bias[col + 1]; }
            *(float2*)(C + (size_t)row0 * N + col) =
                make_float2(acc[mf][nf][0] + b0, acc[mf][nf][1] + b1);
            *(float2*)(C + (size_t)(row0 + 8) * N + col) =
                make_float2(acc[mf][nf][2] + b0, acc[mf][nf][3] + b1);
        }
    }
}

// ---------------------------------------------------------------------------
// Flash attention with tf32 mma + FMA-pipe softmax.
// One CTA = (batch*head, 64-query block). 8 warps (2m x 4n), warp tile 32x16.
// ---------------------------------------------------------------------------
#define QP 68
#define KP 68
#define SP 68
#define VP 72
#define F_SQ 0
#define F_SK (F_SQ + 64 * QP)
#define F_SS (F_SK + 64 * KP)
#define F_SV (F_SS + 64 * SP)
#define F_SM (F_SV + 64 * VP)
#define F_SL (F_SM + 64)
#define F_SAL (F_SL + 64)
#define FSMEM_F (F_SAL + 64)
#define FSMEM_BYTES (FSMEM_F * 4)        // 71424

__global__ __launch_bounds__(256) void flash_attn_kernel(
    const float* __restrict__ qkv, float* __restrict__ outp)
{
    extern __shared__ float sm[];
    float* sQ = sm + F_SQ;
    float* sK = sm + F_SK;
    float* sS = sm + F_SS;
    float* sV = sm + F_SV;
    float* sMx = sm + F_SM;
    float* sL = sm + F_SL;
    float* sAl = sm + F_SAL;

    const int tid = threadIdx.x;
    const int wid = tid >> 5, lane = tid & 31;
    const int wm = wid >> 2, wn = wid & 3;      // 2 x 4
    const int l4 = lane >> 2, lm4 = lane & 3;

    const int qblk = blockIdx.x;                // 0..31
    const int bh = blockIdx.y;                  // 0..63
    const int b = bh >> 4, h = bh & 15;

    const size_t rowStride = QKV_COLS;
    const float* qb = qkv + (size_t)b * GN * rowStride + (size_t)h * GDH;
    const float* kb = qb + GINNER;
    const float* vb = qb + 2 * GINNER;

    // Load Q (scaled + tf32-rounded), init stats
#pragma unroll
    for (int i = 0; i < 4; i++) {
        int c = tid + i * 256;
        int r = c >> 4, c4 = (c & 15) * 4;
        float4 v = *(const float4*)(qb + (size_t)(qblk * 64 + r) * rowStride + c4);
        v.x = rtf(v.x * 0.125f); v.y = rtf(v.y * 0.125f);
        v.z = rtf(v.z * 0.125f); v.w = rtf(v.w * 0.125f);
        *(float4*)(sQ + r * QP + c4) = v;
    }
    if (tid < 64) { sMx[tid] = -3.0e38f; sL[tid] = 0.f; }

    float o[2][2][4];
#pragma unroll
    for (int mf = 0; mf < 2; mf++)
#pragma unroll
        for (int nf = 0; nf < 2; nf++)
#pragma unroll
            for (int r = 0; r < 4; r++) o[mf][nf][r] = 0.f;

    for (int jj = 0; jj < GN / 64; jj++) {
        __syncthreads();   // Q ready / prev PV done with sK,sV,sS

        // Load K, V tiles (tf32-rounded)
#pragma unroll
        for (int i = 0; i < 4; i++) {
            int c = tid + i * 256;
            int r = c >> 4, c4 = (c & 15) * 4;
            size_t g = (size_t)(jj * 64 + r) * rowStride + c4;
            float4 kv = *(const float4*)(kb + g);
            kv.x = rtf(kv.x); kv.y = rtf(kv.y); kv.z = rtf(kv.z); kv.w = rtf(kv.w);
            *(float4*)(sK + r * KP + c4) = kv;
            float4 vv = *(const float4*)(vb + g);
            vv.x = rtf(vv.x); vv.y = rtf(vv.y); vv.z = rtf(vv.z); vv.w = rtf(vv.w);
            *(float4*)(sV + r * VP + c4) = vv;
        }
        __syncthreads();

        // ---- S = Q @ K^T via mma ----
        float sacc[2][2][4];
#pragma unroll
        for (int mf = 0; mf < 2; mf++)
#pragma unroll
            for (int nf = 0; nf < 2; nf++)
#pragma unroll
                for (int r = 0; r < 4; r++) sacc[mf][nf][r] = 0.f;

#pragma unroll
        for (int ks = 0; ks < 8; ks++) {
            int kk = ks * 8 + lm4;
            uint32_t a[2][4], bfr[2][2];
            const uint32_t* Qu = (const uint32_t*)sQ;
            const uint32_t* Ku = (const uint32_t*)sK;
#pragma unroll
            for (int mf = 0; mf < 2; mf++) {
                int m = wm * 32 + mf * 16 + l4;
                a[mf][0] = Qu[m * QP + kk];
                a[mf][1] = Qu[(m + 8) * QP + kk];
                a[mf][2] = Qu[m * QP + kk + 4];
                a[mf][3] = Qu[(m + 8) * QP + kk + 4];
            }
#pragma unroll
            for (int nf = 0; nf < 2; nf++) {
                int n = wn * 16 + nf * 8 + l4;
                bfr[nf][0] = Ku[n * KP + kk];
                bfr[nf][1] = Ku[n * KP + kk + 4];
            }
#pragma unroll
            for (int mf = 0; mf < 2; mf++)
#pragma unroll
                for (int nf = 0; nf < 2; nf++)
                    mma_tf32(sacc[mf][nf], a[mf], bfr[nf]);
        }
        // write S fragments
#pragma unroll
        for (int mf = 0; mf < 2; mf++) {
            int row = wm * 32 + mf * 16 + l4;
#pragma unroll
            for (int nf = 0; nf < 2; nf++) {
                int col = wn * 16 + nf * 8 + lm4 * 2;
                *(float2*)(sS + row * SP + col) =
                    make_float2(sacc[mf][nf][0], sacc[mf][nf][1]);
                *(float2*)(sS + (row + 8) * SP + col) =
                    make_float2(sacc[mf][nf][2], sacc[mf][nf][3]);
            }
        }
        __syncthreads();

        // ---- online softmax (4 threads/row), FMA-pipe exp, P -> tf32 ----
        {
            int row = tid >> 2, part = tid & 3;
            float* base = &sS[row * SP + part * 16];
            float mloc = -3.0e38f;
#pragma unroll
            for (int t = 0; t < 16; t++) mloc = fmaxf(mloc, base[t]);
            mloc = fmaxf(mloc, __shfl_xor_sync(0xffffffffu, mloc, 1));
            mloc = fmaxf(mloc, __shfl_xor_sync(0xffffffffu, mloc, 2));
            float mold = sMx[row];
            float mnew = fmaxf(mold, mloc);
            float suml = 0.f;
#pragma unroll
            for (int t = 0; t < 16; t++) {
                float p = fast_exp_tf32(base[t] - mnew);
                base[t] = p;
                suml += p;
            }
            suml += __shfl_xor_sync(0xffffffffu, suml, 1);
            suml += __shfl_xor_sync(0xffffffffu, suml, 2);
            if (part == 0) {
                float al = fast_exp(mold - mnew);
                sAl[row] = al;
                sMx[row] = mnew;
                sL[row] = sL[row] * al + suml;
            }
        }
        __syncthreads();

        // ---- O = O*alpha + P @ V via mma ----
#pragma unroll
        for (int mf = 0; mf < 2; mf++) {
            float al0 = sAl[wm * 32 + mf * 16 + l4];
            float al1 = sAl[wm * 32 + mf * 16 + l4 + 8];
#pragma unroll
            for (int nf = 0; nf < 2; nf++) {
                o[mf][nf][0] *= al0; o[mf][nf][1] *= al0;
                o[mf][nf][2] *= al1; o[mf][nf][3] *= al1;
            }
        }
#pragma unroll
        for (int ks = 0; ks < 8; ks++) {
            int kk = ks * 8 + lm4;
            uint32_t a[2][4], bfr[2][2];
            const uint32_t* Su = (const uint32_t*)sS;
            const uint32_t* Vu = (const uint32_t*)sV;
#pragma unroll
            for (int mf = 0; mf < 2; mf++) {
                int m = wm * 32 + mf * 16 + l4;
                a[mf][0] = Su[m * SP + kk];
                a[mf][1] = Su[(m + 8) * SP + kk];
                a[mf][2] = Su[m * SP + kk + 4];
                a[mf][3] = Su[(m + 8) * SP + kk + 4];
            }
#pragma unroll
            for (int nf = 0; nf < 2; nf++) {
                int n = wn * 16 + nf * 8 + l4;
                bfr[nf][0] = Vu[kk * VP + n];
                bfr[nf][1] = Vu[(kk + 4) * VP + n];
            }
#pragma unroll
            for (int mf = 0; mf < 2; mf++)
#pragma unroll
                for (int nf = 0; nf < 2; nf++)
                    mma_tf32(o[mf][nf], a[mf], bfr[nf]);
        }
    }

    // Normalize and write (tf32-rounded: feeds GEMM2 directly)
#pragma unroll
    for (int mf = 0; mf < 2; mf++) {
        int r0g = wm * 32 + mf * 16 + l4;
        float inv0 = 1.f / sL[r0g];
        float inv1 = 1.f / sL[r0g + 8];
#pragma unroll
        for (int nf = 0; nf < 2; nf++) {
            int col = h * GDH + wn * 16 + nf * 8 + lm4 * 2;
            size_t i0 = (size_t)(b * GN + qblk * 64 + r0g) * GINNER + col;
            size_t i1 = (size_t)(b * GN + qblk * 64 + r0g + 8) * GINNER + col;
            *(float2*)(outp + i0) =
                make_float2(rtf(o[mf][nf][0] * inv0), rtf(o[mf][nf][1] * inv0));
            *(float2*)(outp + i1) =
                make_float2(rtf(o[mf][nf][2] * inv1), rtf(o[mf][nf][3] * inv1));
        }
    }
}

// ---------------------------------------------------------------------------
// Elementwise tf32 rounding (operand prep)
// ---------------------------------------------------------------------------
__global__ void round_tf32_kernel(const float* __restrict__ in,
                                  float* __restrict__ out, int n4)
{
    int i = blockIdx.x * blockDim.x + threadIdx.x;
    if (i < n4) {
        float4 v = ((const float4*)in)[i];
        v.x = rtf(v.x); v.y = rtf(v.y); v.z = rtf(v.z); v.w = rtf(v.w);
        ((float4*)out)[i] = v;
    }
}

// ---------------------------------------------------------------------------
// Launch
// ---------------------------------------------------------------------------
extern "C" void kernel_launch(void* const* d_in, const int* in_sizes, int n_in,
                              void* d_out, int out_size)
{
    const float* x     = (const float*)d_in[0];
    const float* w_qkv = (const float*)d_in[1];
    const float* w_out = (const float*)d_in[2];
    const float* b_out = (const float*)d_in[3];
    float* out = (float*)d_out;

    float *qkv_p, *attn_p, *xr_p, *wqkvr_p, *woutr_p;
    cudaGetSymbolAddress((void**)&qkv_p, g_qkv);
    cudaGetSymbolAddress((void**)&attn_p, g_attn);
    cudaGetSymbolAddress((void**)&xr_p, g_xr);
    cudaGetSymbolAddress((void**)&wqkvr_p, g_wqkvr);
    cudaGetSymbolAddress((void**)&woutr_p, g_woutr);

    cudaFuncSetAttribute(gemm_tf32_kernel,
                         cudaFuncAttributeMaxDynamicSharedMemorySize, GSMEM_BYTES);
    cudaFuncSetAttribute(flash_attn_kernel,
                         cudaFuncAttributeMaxDynamicSharedMemorySize, FSMEM_BYTES);

    // Operand prep (tf32 RN rounding)
    {
        int n4 = (M_ROWS * GDIM) / 4;
        round_tf32_kernel<<<(n4 + 255) / 256, 256>>>(x, xr_p, n4);
    }
    {
        int n4 = (GDIM * QKV_COLS) / 4;
        round_tf32_kernel<<<(n4 + 255) / 256, 256>>>(w_qkv, wqkvr_p, n4);
    }
    {
        int n4 = (GINNER * GDIM) / 4;
        round_tf32_kernel<<<(n4 + 255) / 256, 256>>>(w_out, woutr_p, n4);
    }

    // 1) qkv = xr @ w_qkv
    gemm_tf32_kernel<<<dim3(QKV_COLS / 128, M_ROWS / 128), 256, GSMEM_BYTES>>>(
        xr_p, wqkvr_p, nullptr, qkv_p, M_ROWS, QKV_COLS, GDIM);

    // 2) flash attention (outputs tf32-rounded)
    flash_attn_kernel<<<dim3(GN / 64, GB * GHEADS), 256, FSMEM_BYTES>>>(
        qkv_p, attn_p);

    // 3) out = attn @ w_out + b_out
    gemm_tf32_kernel<<<dim3(GDIM / 128, M_ROWS / 128), 256, GSMEM_BYTES>>>(
        attn_p, woutr_p, b_out, out, M_ROWS, GDIM, GINNER);
}

// round 4
// speedup vs baseline: 3.7384x; 1.3320x over previous
#include <cuda_runtime.h>
#include <math.h>
#include <stdint.h>

// Problem constants
#define GB 4
#define GN 2048
#define GDIM 1024
#define GHEADS 16
#define GDH 64
#define GINNER 1024
#define M_ROWS (GB * GN)          // 8192
#define QKV_COLS (3 * GINNER)     // 3072

// Scratch (__device__ globals; no allocations allowed)
__device__ float g_qkv[M_ROWS * QKV_COLS];     // [8192, 3072] (tf32-rounded)
__device__ float g_attn[M_ROWS * GINNER];      // [8192, 1024] (tf32-rounded)
__device__ float g_xr[M_ROWS * GDIM];          // tf32-rounded x
__device__ float g_wqkvr[GDIM * QKV_COLS];     // tf32-rounded w_qkv [K,N]
__device__ float g_woutr[GINNER * GDIM];       // tf32-rounded w_out [K,N]
__device__ float g_vT[64 * GDH * GN];          // V transposed: [bh][feat][token]

// ---------------------------------------------------------------------------
// Helpers (compute_100-safe PTX only)
// ---------------------------------------------------------------------------
__device__ __forceinline__ uint32_t smem_u32(const void* p) {
    uint32_t a;
    asm("{ .reg .u64 t; cvta.to.shared.u64 t, %1; cvt.u32.u64 %0, t; }"
        : "=r"(a) : "l"(p));
    return a;
}
__device__ __forceinline__ void cp_async16(uint32_t dst, const void* src) {
    asm volatile("cp.async.cg.shared.global [%0], [%1], 16;" :: "r"(dst), "l"(src));
}
#define CP_COMMIT() asm volatile("cp.async.commit_group;" ::: "memory")
template <int N>
__device__ __forceinline__ void cp_wait() {
    asm volatile("cp.async.wait_group %0;" :: "n"(N) : "memory");
}

// Round fp32 -> tf32 (round-to-nearest)
__device__ __forceinline__ float rtf(float x) {
    return __int_as_float((__float_as_int(x) + 0x1000) & 0xFFFFE000);
}

// ldmatrix x4 (b16 granularity; an 8x4 fp32 tile per matrix:
// thread t gets fp32 element [row t/4][col t%4] of matrix t/8)
__device__ __forceinline__ void ldsm4(uint32_t* r, uint32_t addr) {
    asm volatile("ldmatrix.sync.aligned.m8n8.x4.shared.b16 {%0,%1,%2,%3}, [%4];"
        : "=r"(r[0]), "=r"(r[1]), "=r"(r[2]), "=r"(r[3]) : "r"(addr));
}

// m16n8k8 tf32 mma, D accumulates in place.
__device__ __forceinline__ void mma_tf32(float* d, const uint32_t* a, const uint32_t* b) {
    asm volatile(
        "mma.sync.aligned.m16n8k8.row.col.f32.tf32.tf32.f32 "
        "{%0,%1,%2,%3}, {%4,%5,%6,%7}, {%8,%9}, {%0,%1,%2,%3};"
        : "+f"(d[0]), "+f"(d[1]), "+f"(d[2]), "+f"(d[3])
        : "r"(a[0]), "r"(a[1]), "r"(a[2]), "r"(a[3]), "r"(b[0]), "r"(b[1]));
}

// ---------------------------------------------------------------------------
// tf32 tensor-core GEMM (unchanged from R2 except optional tf32-rounded out)
// ---------------------------------------------------------------------------
#define A_PAD 36
#define B_PAD 136
#define A_F (128 * A_PAD)
#define B_F (32 * B_PAD)
#define STAGE_F (A_F + B_F)
#define GSMEM_BYTES (3 * STAGE_F * 4)

__global__ __launch_bounds__(256, 2) void gemm_tf32_kernel(
    const float* __restrict__ A, const float* __restrict__ B,
    const float* __restrict__ bias, float* __restrict__ C,
    int M, int N, int K, int roundOut)
{
    extern __shared__ float smem[];
    const uint32_t sb = smem_u32(smem);

    const int tid = threadIdx.x;
    const int wid = tid >> 5, lane = tid & 31;
    const int wm = wid >> 2, wn = wid & 3;
    const int l4 = lane >> 2, lm4 = lane & 3;

    const int nb = blockIdx.x, mb = blockIdx.y;
    const int rowBase = mb * 128, colBase = nb * 128;
    const float* Ag = A + (size_t)rowBase * K;
    const float* Bg = B + colBase;
    const int KT = K >> 5;

    float acc[4][4][4];
#pragma unroll
    for (int i = 0; i < 4; i++)
#pragma unroll
        for (int j = 0; j < 4; j++)
#pragma unroll
            for (int r = 0; r < 4; r++) acc[i][j][r] = 0.f;

#define LOAD_STAGE(kt, slot) do {                                            \
    uint32_t _sa = sb + (slot) * STAGE_F * 4;                                \
    uint32_t _sb2 = _sa + A_F * 4;                                           \
    _Pragma("unroll")                                                        \
    for (int _i = 0; _i < 4; _i++) {                                         \
        int _c = tid + _i * 256;                                             \
        int _r = _c >> 3, _kc = _c & 7;                                      \
        cp_async16(_sa + _r * (A_PAD * 4) + _kc * 16,                        \
                   Ag + (size_t)_r * K + (kt) * 32 + _kc * 4);               \
    }                                                                        \
    _Pragma("unroll")                                                        \
    for (int _i = 0; _i < 4; _i++) {                                         \
        int _c = tid + _i * 256;                                             \
        int _kr = _c >> 5, _nc = _c & 31;                                    \
        cp_async16(_sb2 + _kr * (B_PAD * 4) + _nc * 16,                      \
                   Bg + (size_t)((kt) * 32 + _kr) * N + _nc * 4);            \
    }                                                                        \
    CP_COMMIT();                                                             \
} while (0)

    LOAD_STAGE(0, 0);
    LOAD_STAGE(1, 1);
    LOAD_STAGE(2, 2);

    for (int k = 0; k < KT; k++) {
        if (k < KT - 2)       cp_wait<2>();
        else if (k == KT - 2) cp_wait<1>();
        else                  cp_wait<0>();
        __syncthreads();

        const float* As = smem + (k % 3) * STAGE_F;
        const float* Bs = As + A_F;

#pragma unroll
        for (int ks = 0; ks < 4; ks++) {
            uint32_t a[4][4], b[4][2];
            int kk = ks * 8 + lm4;
#pragma unroll
            for (int mf = 0; mf < 4; mf++) {
                int m = wm * 64 + mf * 16 + l4;
                const uint32_t* Au = (const uint32_t*)As;
                a[mf][0] = Au[m * A_PAD + kk];
                a[mf][1] = Au[(m + 8) * A_PAD + kk];
                a[mf][2] = Au[m * A_PAD + kk + 4];
                a[mf][3] = Au[(m + 8) * A_PAD + kk + 4];
            }
#pragma unroll
            for (int nf = 0; nf < 4; nf++) {
                int n = wn * 32 + nf * 8 + l4;
                const uint32_t* Bu = (const uint32_t*)Bs;
                b[nf][0] = Bu[kk * B_PAD + n];
                b[nf][1] = Bu[(kk + 4) * B_PAD + n];
            }
#pragma unroll
            for (int mf = 0; mf < 4; mf++)
#pragma unroll
                for (int nf = 0; nf < 4; nf++)
                    mma_tf32(acc[mf][nf], a[mf], b[nf]);
        }
        __syncthreads();

        if (k + 3 < KT) LOAD_STAGE(k + 3, k % 3);
    }
#undef LOAD_STAGE

#pragma unroll
    for (int mf = 0; mf < 4; mf++) {
        int row0 = rowBase + wm * 64 + mf * 16 + l4;
#pragma unroll
        for (int nf = 0; nf < 4; nf++) {
            int col = colBase + wn * 32 + nf * 8 + lm4 * 2;
            float b0 = 0.f, b1 = 0.f;
            if (bias) { b0 = bias[col]; b1 = bias[col + 1]; }
            float v0 = acc[mf][nf][0] + b0, v1 = acc[mf][nf][1] + b1;
            float v2 = acc[mf][nf][2] + b0, v3 = acc[mf][nf][3] + b1;
            if (roundOut) { v0 = rtf(v0); v1 = rtf(v1); v2 = rtf(v2); v3 = rtf(v3); }
            *(float2*)(C + (size_t)row0 * N + col) = make_float2(v0, v1);
            *(float2*)(C + (size_t)(row0 + 8) * N + col) = make_float2(v2, v3);
        }
    }
}

// ---------------------------------------------------------------------------
// V transpose: g_qkv V-part [token][h*64+d] -> g_vT [bh][d][token]
// ---------------------------------------------------------------------------
__global__ void transpose_v_kernel(const float* __restrict__ qkv,
                                   float* __restrict__ vT)
{
    __shared__ float t[32][33];
    int bh = blockIdx.z, b = bh >> 4, h = bh & 15;
    int tok0 = blockIdx.x * 32;
    int f0 = blockIdx.y * 32;
    int tx = threadIdx.x, ty = threadIdx.y;   // 32 x 8
#pragma unroll
    for (int i = 0; i < 4; i++) {
        int tok = tok0 + ty + i * 8;
        t[ty + i * 8][tx] =
            qkv[(size_t)(b * GN + tok) * QKV_COLS + 2 * GINNER + h * GDH + f0 + tx];
    }
    __syncthreads();
#pragma unroll
    for (int i = 0; i < 4; i++) {
        int f = f0 + ty + i * 8;
        vT[((size_t)bh * GDH + f) * GN + tok0 + tx] = t[tx][ty + i * 8];
    }
}

// ---------------------------------------------------------------------------
// Flash attention v2: 256-query CTA, 8 warps x 32 queries (full rows per
// warp), cp.async 4-stage K/Vt pipeline, ldmatrix fragments, register-resident
// online softmax, P->A-fragment via quad shuffles.
// ---------------------------------------------------------------------------
#define QP2 68
#define KVP (64 * 68)                 // floats per K or Vt tile
#define STAGE2_F (2 * KVP)            // 8704
#define SQ_F (256 * QP2)              // 17408
#define ASMEM_F (SQ_F + 4 * STAGE2_F) // 52224
#define ASMEM_BYTES (ASMEM_F * 4)     // 208896

__global__ __launch_bounds__(256) void flash_attn_kernel(
    const float* __restrict__ qkv, const float* __restrict__ vT,
    float* __restrict__ outp)
{
    extern __shared__ float sm[];
    const uint32_t sm0 = smem_u32(sm);
    const int tid = threadIdx.x;
    const int wid = tid >> 5, lane = tid & 31;
    const int gid = lane >> 2, tid4 = lane & 3;
    const int mm = lane >> 3;              // ldmatrix.x4 matrix id
    const int mrow8 = (mm & 1) * 8;
    const int mcol4 = (mm >> 1) * 4;
    const int lrow = lane & 7;

    const int qblk = blockIdx.x;           // 0..7
    const int bh = blockIdx.y;             // 0..63
    const int b = bh >> 4, h = bh & 15;
    const int qbase = qblk * 256;

    const float* qsrc = qkv + (size_t)(b * GN + qbase) * QKV_COLS + h * GDH;
    const float* ksrc = qkv + (size_t)(b * GN) * QKV_COLS + GINNER + h * GDH;
    const float* vtsrc = vT + (size_t)bh * GDH * GN;   // [64][2048]

    // Q tile: 256 rows x 64 floats (16 chunks/row)
#pragma unroll
    for (int i = 0; i < 16; i++) {
        int c = tid + i * 256, r = c >> 4, ch = c & 15;
        cp_async16(sm0 + (uint32_t)(r * QP2 + ch * 4) * 4u,
                   qsrc + (size_t)r * QKV_COLS + ch * 4);
    }
    CP_COMMIT();

#define LOAD_KV(kt, slot) do {                                               \
    uint32_t _bb = sm0 + (uint32_t)(SQ_F + (slot) * STAGE2_F) * 4u;          \
    _Pragma("unroll")                                                        \
    for (int _i = 0; _i < 4; _i++) {                                         \
        int _c = tid + _i * 256, _r = _c >> 4, _ch = _c & 15;                \
        cp_async16(_bb + (uint32_t)(_r * 68 + _ch * 4) * 4u,                 \
                   ksrc + (size_t)((kt) * 64 + _r) * QKV_COLS + _ch * 4);    \
    }                                                                        \
    _Pragma("unroll")                                                        \
    for (int _i = 0; _i < 4; _i++) {                                         \
        int _c = tid + _i * 256, _r = _c >> 4, _ch = _c & 15;                \
        cp_async16(_bb + (uint32_t)(KVP + _r * 68 + _ch * 4) * 4u,           \
                   vtsrc + (size_t)_r * GN + (kt) * 64 + _ch * 4);           \
    }                                                                        \
    CP_COMMIT();                                                             \
} while (0)

    LOAD_KV(0, 0); LOAD_KV(1, 1); LOAD_KV(2, 2);

    cp_wait<3>();                 // Q complete (per-thread)
    __syncthreads();
    // scale Q by d^-0.5 = 0.125 (exact power of 2 -> stays tf32)
    for (int i = tid; i < SQ_F; i += 256) sm[i] *= 0.125f;

    const int Rw = wid * 32;

    float o[2][8][4];
    float mrun[2][2], lrun[2][2];
#pragma unroll
    for (int mt = 0; mt < 2; mt++) {
#pragma unroll
        for (int nt = 0; nt < 8; nt++)
#pragma unroll
            for (int c = 0; c < 4; c++) o[mt][nt][c] = 0.f;
        mrun[mt][0] = mrun[mt][1] = -1e30f;
        lrun[mt][0] = lrun[mt][1] = 0.f;
    }

    for (int it = 0; it < GN / 64; it++) {
        cp_wait<2>();             // stage it complete
        __syncthreads();          // visible to all; prev-prev slot free
        if (it + 3 < GN / 64) LOAD_KV(it + 3, (it + 3) & 3);

        const uint32_t kB = sm0 + (uint32_t)(SQ_F + (it & 3) * STAGE2_F) * 4u;
        const uint32_t vB = kB + (uint32_t)KVP * 4u;

        // ---- S = Q @ K^T ----
        float sacc[2][8][4];
#pragma unroll
        for (int mt = 0; mt < 2; mt++)
#pragma unroll
            for (int nt = 0; nt < 8; nt++)
#pragma unroll
                for (int c = 0; c < 4; c++) sacc[mt][nt][c] = 0.f;

#pragma unroll
        for (int ks = 0; ks < 8; ks++) {
            uint32_t aq[2][4];
#pragma unroll
            for (int mt = 0; mt < 2; mt++) {
                uint32_t addr = sm0
                    + (uint32_t)((Rw + mt * 16 + mrow8 + lrow) * QP2) * 4u
                    + (uint32_t)(ks * 8 + mcol4) * 4u;
                ldsm4(aq[mt], addr);
            }
#pragma unroll
            for (int p = 0; p < 4; p++) {
                uint32_t bk[4];
                uint32_t addr = kB
                    + (uint32_t)(((p * 2 + (mm >> 1)) * 8 + lrow) * 68) * 4u
                    + (uint32_t)(ks * 8 + (mm & 1) * 4) * 4u;
                ldsm4(bk, addr);
                mma_tf32(sacc[0][p * 2],     aq[0], bk);
                mma_tf32(sacc[0][p * 2 + 1], aq[0], bk + 2);
                mma_tf32(sacc[1][p * 2],     aq[1], bk);
                mma_tf32(sacc[1][p * 2 + 1], aq[1], bk + 2);
            }
        }

        // ---- register-resident online softmax (warp-local rows) ----
#pragma unroll
        for (int mt = 0; mt < 2; mt++) {
            float mx0 = -1e30f, mx1 = -1e30f;
#pragma unroll
            for (int nt = 0; nt < 8; nt++) {
                mx0 = fmaxf(mx0, fmaxf(sacc[mt][nt][0], sacc[mt][nt][1]));
                mx1 = fmaxf(mx1, fmaxf(sacc[mt][nt][2], sacc[mt][nt][3]));
            }
            mx0 = fmaxf(mx0, __shfl_xor_sync(0xffffffffu, mx0, 1));
            mx0 = fmaxf(mx0, __shfl_xor_sync(0xffffffffu, mx0, 2));
            mx1 = fmaxf(mx1, __shfl_xor_sync(0xffffffffu, mx1, 1));
            mx1 = fmaxf(mx1, __shfl_xor_sync(0xffffffffu, mx1, 2));
            float mn0 = fmaxf(mrun[mt][0], mx0);
            float mn1 = fmaxf(mrun[mt][1], mx1);
            float al0 = __expf(mrun[mt][0] - mn0);
            float al1 = __expf(mrun[mt][1] - mn1);
            mrun[mt][0] = mn0; mrun[mt][1] = mn1;
            float s0 = 0.f, s1 = 0.f;
#pragma unroll
            for (int nt = 0; nt < 8; nt++) {
                float p0 = rtf(__expf(sacc[mt][nt][0] - mn0));
                float p1 = rtf(__expf(sacc[mt][nt][1] - mn0));
                float p2 = rtf(__expf(sacc[mt][nt][2] - mn1));
                float p3 = rtf(__expf(sacc[mt][nt][3] - mn1));
                sacc[mt][nt][0] = p0; sacc[mt][nt][1] = p1;
                sacc[mt][nt][2] = p2; sacc[mt][nt][3] = p3;
                s0 += p0 + p1; s1 += p2 + p3;
                o[mt][nt][0] *= al0; o[mt][nt][1] *= al0;
                o[mt][nt][2] *= al1; o[mt][nt][3] *= al1;
            }
            s0 += __shfl_xor_sync(0xffffffffu, s0, 1);
            s0 += __shfl_xor_sync(0xffffffffu, s0, 2);
            s1 += __shfl_xor_sync(0xffffffffu, s1, 1);
            s1 += __shfl_xor_sync(0xffffffffu, s1, 2);
            lrun[mt][0] = lrun[mt][0] * al0 + s0;
            lrun[mt][1] = lrun[mt][1] * al1 + s1;
        }

        // ---- O += P @ V : P accum -> A-frags via quad shuffles ----
        const int srcA = (lane & 28) | (tid4 >> 1);
        const int srcB = srcA + 2;
        const int odd = tid4 & 1;
#pragma unroll
        for (int t = 0; t < 8; t++) {
            uint32_t ap[2][4];
#pragma unroll
            for (int mt = 0; mt < 2; mt++) {
                float e0 = __shfl_sync(0xffffffffu, sacc[mt][t][0], srcA);
                float e1 = __shfl_sync(0xffffffffu, sacc[mt][t][1], srcA);
                float e2 = __shfl_sync(0xffffffffu, sacc[mt][t][2], srcA);
                float e3 = __shfl_sync(0xffffffffu, sacc[mt][t][3], srcA);
                float f0 = __shfl_sync(0xffffffffu, sacc[mt][t][0], srcB);
                float f1 = __shfl_sync(0xffffffffu, sacc[mt][t][1], srcB);
                float f2 = __shfl_sync(0xffffffffu, sacc[mt][t][2], srcB);
                float f3 = __shfl_sync(0xffffffffu, sacc[mt][t][3], srcB);
                ap[mt][0] = __float_as_uint(odd ? e1 : e0);
                ap[mt][1] = __float_as_uint(odd ? e3 : e2);
                ap[mt][2] = __float_as_uint(odd ? f1 : f0);
                ap[mt][3] = __float_as_uint(odd ? f3 : f2);
            }
#pragma unroll
            for (int p = 0; p < 4; p++) {
                uint32_t bv[4];
                uint32_t addr = vB
                    + (uint32_t)(((p * 2 + (mm >> 1)) * 8 + lrow) * 68) * 4u
                    + (uint32_t)(t * 8 + (mm & 1) * 4) * 4u;
                ldsm4(bv, addr);
                mma_tf32(o[0][p * 2],     ap[0], bv);
                mma_tf32(o[0][p * 2 + 1], ap[0], bv + 2);
                mma_tf32(o[1][p * 2],     ap[1], bv);
                mma_tf32(o[1][p * 2 + 1], ap[1], bv + 2);
            }
        }
    }
#undef LOAD_KV

    // ---- normalize + write (tf32-rounded: feeds GEMM2) ----
#pragma unroll
    for (int mt = 0; mt < 2; mt++) {
        float i0 = 1.f / lrun[mt][0], i1 = 1.f / lrun[mt][1];
        int r0g = qbase + Rw + mt * 16 + gid;
#pragma unroll
        for (int nt = 0; nt < 8; nt++) {
            int col = h * GDH + nt * 8 + tid4 * 2;
            size_t o0 = (size_t)(b * GN + r0g) * GINNER + col;
            size_t o1 = (size_t)(b * GN + r0g + 8) * GINNER + col;
            *(float2*)(outp + o0) =
                make_float2(rtf(o[mt][nt][0] * i0), rtf(o[mt][nt][1] * i0));
            *(float2*)(outp + o1) =
                make_float2(rtf(o[mt][nt][2] * i1), rtf(o[mt][nt][3] * i1));
        }
    }
}

// ---------------------------------------------------------------------------
// Elementwise tf32 rounding (operand prep)
// ---------------------------------------------------------------------------
__global__ void round_tf32_kernel(const float* __restrict__ in,
                                  float* __restrict__ out, int n4)
{
    int i = blockIdx.x * blockDim.x + threadIdx.x;
    if (i < n4) {
        float4 v = ((const float4*)in)[i];
        v.x = rtf(v.x); v.y = rtf(v.y); v.z = rtf(v.z); v.w = rtf(v.w);
        ((float4*)out)[i] = v;
    }
}

// ---------------------------------------------------------------------------
// Launch
// ---------------------------------------------------------------------------
extern "C" void kernel_launch(void* const* d_in, const int* in_sizes, int n_in,
                              void* d_out, int out_size)
{
    const float* x     = (const float*)d_in[0];
    const float* w_qkv = (const float*)d_in[1];
    const float* w_out = (const float*)d_in[2];
    const float* b_out = (const float*)d_in[3];
    float* out = (float*)d_out;

    float *qkv_p, *attn_p, *xr_p, *wqkvr_p, *woutr_p, *vT_p;
    cudaGetSymbolAddress((void**)&qkv_p, g_qkv);
    cudaGetSymbolAddress((void**)&attn_p, g_attn);
    cudaGetSymbolAddress((void**)&xr_p, g_xr);
    cudaGetSymbolAddress((void**)&wqkvr_p, g_wqkvr);
    cudaGetSymbolAddress((void**)&woutr_p, g_woutr);
    cudaGetSymbolAddress((void**)&vT_p, g_vT);

    cudaFuncSetAttribute(gemm_tf32_kernel,
                         cudaFuncAttributeMaxDynamicSharedMemorySize, GSMEM_BYTES);
    cudaFuncSetAttribute(flash_attn_kernel,
                         cudaFuncAttributeMaxDynamicSharedMemorySize, ASMEM_BYTES);

    // Operand prep (tf32 RN rounding)
    {
        int n4 = (M_ROWS * GDIM) / 4;
        round_tf32_kernel<<<(n4 + 255) / 256, 256>>>(x, xr_p, n4);
    }
    {
        int n4 = (GDIM * QKV_COLS) / 4;
        round_tf32_kernel<<<(n4 + 255) / 256, 256>>>(w_qkv, wqkvr_p, n4);
    }
    {
        int n4 = (GINNER * GDIM) / 4;
        round_tf32_kernel<<<(n4 + 255) / 256, 256>>>(w_out, woutr_p, n4);
    }

    // 1) qkv = xr @ w_qkv  (output tf32-rounded for attention mma)
    gemm_tf32_kernel<<<dim3(QKV_COLS / 128, M_ROWS / 128), 256, GSMEM_BYTES>>>(
        xr_p, wqkvr_p, nullptr, qkv_p, M_ROWS, QKV_COLS, GDIM, 1);

    // 2) V transpose for ldmatrix-friendly PV fragments
    transpose_v_kernel<<<dim3(GN / 32, GDH / 32, 64), dim3(32, 8)>>>(qkv_p, vT_p);

    // 3) flash attention (outputs tf32-rounded)
    flash_attn_kernel<<<dim3(GN / 256, 64), 256, ASMEM_BYTES>>>(
        qkv_p, vT_p, attn_p);

    // 4) out = attn @ w_out + b_out
    gemm_tf32_kernel<<<dim3(GDIM / 128, M_ROWS / 128), 256, GSMEM_BYTES>>>(
        attn_p, woutr_p, b_out, out, M_ROWS, GDIM, GINNER, 0);
}